// round 5
// baseline (speedup 1.0000x reference)
#include <cuda_runtime.h>
#include <cuda_bf16.h>
#include <math.h>

// Problem constants
#define B   64
#define C   512
#define CP  128
#define HH  32
#define WW  32
#define HW  1024
#define NSEL (B*CP*HW)       // 8388608
#define NALL (B*C*HW)        // 33554432

// ---------------- scratch (device globals; no allocs allowed) ----------------
__device__ float g_pooled[B*2*C];
__device__ float g_ca[B*C];
__device__ float g_slist[C];
__device__ int   g_idx[CP];
__device__ float g_xtemp[NSEL];
__device__ float g_t1[NSEL];
__device__ float g_t2[NSEL];
__device__ float g_acc[NSEL];
__device__ float g_mean[CP];
__device__ float g_rstd[CP];

// ---------------- 1. per-(b,c) avg + max over HW ----------------
__global__ void pool_reduce_kernel(const float* __restrict__ x) {
    int bc = blockIdx.x;                     // b*C + c
    const float* p = x + (size_t)bc * HW;
    int tid = threadIdx.x;                   // 128 threads
    float s = 0.f, m = -INFINITY;
    for (int i = tid; i < HW; i += 128) { float v = p[i]; s += v; m = fmaxf(m, v); }
    __shared__ float ss[128], sm[128];
    ss[tid] = s; sm[tid] = m; __syncthreads();
    for (int st = 64; st > 0; st >>= 1) {
        if (tid < st) { ss[tid] += ss[tid+st]; sm[tid] = fmaxf(sm[tid], sm[tid+st]); }
        __syncthreads();
    }
    if (tid == 0) {
        int b = bc >> 9, c = bc & 511;
        g_pooled[b*2*C + c]     = ss[0] * (1.f/1024.f);
        g_pooled[b*2*C + C + c] = sm[0];
    }
}

// ---------------- 2. channel attention MLP ----------------
__global__ void attention_kernel(const float* __restrict__ fc1,
                                 const float* __restrict__ wa,
                                 const float* __restrict__ fc2) {
    int b = blockIdx.x, tid = threadIdx.x;   // 128 threads
    __shared__ float red[128];
    __shared__ float s_y[10], s_A[100], s_y2[10];
    const float* pr = g_pooled + b*2*C;
    for (int j = 0; j < 10; j++) {
        float local = 0.f;
        for (int i = tid; i < 2*C; i += 128) local += pr[i] * fc1[j*2*C + i];
        red[tid] = local; __syncthreads();
        for (int st = 64; st > 0; st >>= 1) { if (tid < st) red[tid] += red[tid+st]; __syncthreads(); }
        if (tid == 0) s_y[j] = red[0];
        __syncthreads();
    }
    if (tid < 100) {
        int j = tid / 10, k = tid % 10;
        float a = 0.f;
        for (int m = 0; m < 14; m++) a += wa[m*10 + j] * wa[m*10 + k];
        s_A[tid] = a;
    }
    __syncthreads();
    if (tid < 10) {
        float v = 0.f;
        for (int k = 0; k < 10; k++) v += s_y[k] * s_A[tid*10 + k];
        s_y2[tid] = fmaxf(v, 0.f);
    }
    __syncthreads();
    for (int c = tid; c < C; c += 128) {
        float v = 0.f;
        for (int j = 0; j < 10; j++) v += s_y2[j] * fc2[c*10 + j];
        g_ca[b*C + c] = 1.f / (1.f + expf(-v));
    }
}

// ---------------- 3. slist + exact lax.top_k ordering ----------------
__global__ void slist_kernel() {
    int c = threadIdx.x;                     // 512 threads
    float s = 0.f;
    for (int b = 0; b < B; b++) s += g_ca[b*C + c];
    g_slist[c] = s;
}

__global__ void topk_kernel() {
    __shared__ float v[C];
    int tid = threadIdx.x;                   // 512 threads
    v[tid] = g_slist[tid]; __syncthreads();
    float mv = v[tid];
    int rank = 0;
    for (int i = 0; i < C; i++) {
        float o = v[i];
        rank += (o > mv) || (o == mv && i < tid);
    }
    if (rank < CP) g_idx[rank] = tid;
}

// ---------------- 4. scale x by ca into d_out ----------------
__global__ void scale_kernel(const float* __restrict__ x, float* __restrict__ out) {
    int n = blockIdx.x * 256 + threadIdx.x;  // < NALL
    out[n] = x[n] * g_ca[n >> 10];
}

// ---------------- 5. gather xtemp = out[:, idx] ----------------
__global__ void gather_kernel(const float* __restrict__ out) {
    int n = blockIdx.x * 256 + threadIdx.x;  // < NSEL
    int b = n >> 17, p = (n >> 10) & 127, hw = n & 1023;
    g_xtemp[n] = out[(((size_t)b*C + g_idx[p]) << 10) + hw];
}

// ---------------- 6. 3x3 max/avg pool (pad 1, count-aware avg) ----------------
template<bool ISMAX>
__global__ void pool3_kernel(const float* __restrict__ in, float* __restrict__ out) {
    int n = blockIdx.x * 256 + threadIdx.x;  // < NSEL
    int hw = n & 1023, y = hw >> 5, x = hw & 31;
    const float* ip = in + ((size_t)(n >> 10) << 10);
    float m = -INFINITY, s = 0.f; int cnt = 0;
    #pragma unroll
    for (int dy = -1; dy <= 1; dy++) {
        int yy = y + dy; if (yy < 0 || yy >= HH) continue;
        #pragma unroll
        for (int dx = -1; dx <= 1; dx++) {
            int xx = x + dx; if (xx < 0 || xx >= WW) continue;
            float v = ip[yy*WW + xx];
            if (ISMAX) m = fmaxf(m, v); else { s += v; cnt++; }
        }
    }
    out[n] = ISMAX ? m : s / (float)cnt;
}

// ---------------- 7. BN stats per channel over (B,H,W) ----------------
__global__ void bn_stats_kernel(const float* __restrict__ t) {
    int c = blockIdx.x, tid = threadIdx.x;   // 256 threads
    float s = 0.f, s2 = 0.f;
    for (int b = 0; b < B; b++) {
        const float* p = t + ((size_t)(b*CP + c) << 10);
        for (int i = tid; i < HW; i += 256) { float v = p[i]; s += v; s2 += v*v; }
    }
    __shared__ double ds[256], ds2[256];
    ds[tid] = s; ds2[tid] = s2; __syncthreads();
    for (int st = 128; st > 0; st >>= 1) {
        if (tid < st) { ds[tid] += ds[tid+st]; ds2[tid] += ds2[tid+st]; }
        __syncthreads();
    }
    if (tid == 0) {
        double m = ds[0] / 65536.0;
        double var = ds2[0] / 65536.0 - m*m;
        g_mean[c] = (float)m;
        g_rstd[c] = rsqrtf((float)var + 1e-5f);
    }
}

// ---------------- 8. depthwise conv (generic k, dil, pad, input transform) ----
// trans: 0=none, 1=relu, 2=bn+relu (uses g_mean/g_rstd of input tensor)
__global__ void dw_conv_kernel(const float* __restrict__ in, float* __restrict__ out,
                               const float* __restrict__ w,
                               int k, int dil, int pad, int trans) {
    int n = blockIdx.x * 256 + threadIdx.x;  // < NSEL
    int hw = n & 1023, c = (n >> 10) & 127;
    int y = hw >> 5, x = hw & 31;
    const float* ip = in + ((size_t)(n >> 10) << 10);
    float mean = 0.f, rstd = 1.f;
    if (trans == 2) { mean = g_mean[c]; rstd = g_rstd[c]; }
    float acc = 0.f;
    for (int i = 0; i < k; i++) {
        int yy = y + i*dil - pad; if (yy < 0 || yy >= HH) continue;
        for (int j = 0; j < k; j++) {
            int xx = x + j*dil - pad; if (xx < 0 || xx >= WW) continue;
            float v = ip[yy*WW + xx];
            if (trans == 1) v = fmaxf(v, 0.f);
            else if (trans == 2) v = fmaxf((v - mean)*rstd, 0.f);
            acc = fmaf(w[(c*k + i)*k + j], v, acc);
        }
    }
    out[n] = acc;
}

// ---------------- 9. dense conv 128->128 (pointwise / 1x7 / 7x1) --------------
// Tile: 64 co x 4 y x 32 x per block, 256 threads, ci chunks of 16.
// TRANS: 0=none, 1=relu on input.
template<int KH, int KW, int TRANS>
__global__ void dense_conv_kernel(const float* __restrict__ in, float* __restrict__ out,
                                  const float* __restrict__ w) {
    constexpr int KK = KH*KW;
    constexpr int PH = (KH-1)/2, PW = (KW-1)/2;
    constexpr int ROWS = 4 + KH - 1;
    constexpr int CPI  = 32 + KW - 1;
    __shared__ float s_in[16][ROWS][CPI];
    __shared__ float s_w[64][16][KK];
    int tid = threadIdx.x;
    int co0 = blockIdx.x * 64, y0 = blockIdx.y * 4, b = blockIdx.z;
    int xcol = tid & 31, cg = tid >> 5;      // 8 co-groups of 8
    float acc[8][4];
    #pragma unroll
    for (int j = 0; j < 8; j++)
        #pragma unroll
        for (int y = 0; y < 4; y++) acc[j][y] = 0.f;

    for (int cc = 0; cc < CP; cc += 16) {
        for (int i = tid; i < 64*16*KK; i += 256) {
            int co = i / (16*KK); int rem = i - co*16*KK;
            int ci = rem / KK;   int t = rem - ci*KK;
            s_w[co][ci][t] = w[((size_t)(co0+co)*CP + cc+ci)*KK + t];
        }
        for (int i = tid; i < 16*ROWS*CPI; i += 256) {
            int ci = i / (ROWS*CPI); int rem = i - ci*ROWS*CPI;
            int r = rem / CPI;       int cx = rem - r*CPI;
            int y = y0 + r - PH, x = cx - PW;
            float v = 0.f;
            if (y >= 0 && y < HH && x >= 0 && x < WW) {
                v = in[(((size_t)b*CP + cc+ci)*HH + y)*WW + x];
                if (TRANS == 1) v = fmaxf(v, 0.f);
            }
            s_in[ci][r][cx] = v;
        }
        __syncthreads();
        for (int ci = 0; ci < 16; ci++) {
            #pragma unroll
            for (int t = 0; t < KK; t++) {
                int kh = t / KW, kw = t - kh*KW;
                float iv[4];
                #pragma unroll
                for (int y = 0; y < 4; y++) iv[y] = s_in[ci][y+kh][xcol+kw];
                #pragma unroll
                for (int j = 0; j < 8; j++) {
                    float wv = s_w[cg*8 + j][ci][t];
                    #pragma unroll
                    for (int y = 0; y < 4; y++) acc[j][y] = fmaf(wv, iv[y], acc[j][y]);
                }
            }
        }
        __syncthreads();
    }
    #pragma unroll
    for (int j = 0; j < 8; j++) {
        int co = co0 + cg*8 + j;
        #pragma unroll
        for (int y = 0; y < 4; y++)
            out[(((size_t)b*CP + co)*HH + y0+y)*WW + xcol] = acc[j][y];
    }
}

// ---------------- 10. weighted accumulate (with optional BN + extra term) -----
__global__ void acc_kernel(const float* __restrict__ src,
                           const float* __restrict__ wv, int wi,
                           int use_bn,
                           const float* __restrict__ extra, int wi_e,
                           int init) {
    int n = blockIdx.x * 256 + threadIdx.x;  // < NSEL
    int c = (n >> 10) & 127;
    float v = src[n];
    if (use_bn) v = (v - g_mean[c]) * g_rstd[c];
    float r = wv[wi] * v;
    if (extra) r += wv[wi_e] * extra[n];
    if (!init) r += g_acc[n];
    g_acc[n] = r;
}

// ---------------- 11. scatter selected channels into d_out --------------------
__global__ void scatter_kernel(float* __restrict__ out) {
    int n = blockIdx.x * 256 + threadIdx.x;  // < NSEL
    int b = n >> 17, p = (n >> 10) & 127, hw = n & 1023;
    out[(((size_t)b*C + g_idx[p]) << 10) + hw] = g_acc[n];
}

// =============================================================================
extern "C" void kernel_launch(void* const* d_in, const int* in_sizes, int n_in,
                              void* d_out, int out_size) {
    const float* x        = (const float*)d_in[0];
    const float* weights  = (const float*)d_in[1];   // (10,)
    const float* wall     = (const float*)d_in[2];   // (14,10)
    const float* w_fc1    = (const float*)d_in[3];   // (10,1024)
    const float* w_fc2    = (const float*)d_in[4];   // (512,10)
    const float* sep3_dw1 = (const float*)d_in[5];
    const float* sep3_pw1 = (const float*)d_in[6];
    const float* sep3_dw2 = (const float*)d_in[7];
    const float* sep3_pw2 = (const float*)d_in[8];
    const float* sep5_dw1 = (const float*)d_in[9];
    const float* sep5_pw1 = (const float*)d_in[10];
    const float* sep5_dw2 = (const float*)d_in[11];
    const float* sep5_pw2 = (const float*)d_in[12];
    const float* sep7_dw1 = (const float*)d_in[13];
    const float* sep7_pw1 = (const float*)d_in[14];
    const float* sep7_dw2 = (const float*)d_in[15];
    const float* sep7_pw2 = (const float*)d_in[16];
    const float* dil3_dw  = (const float*)d_in[17];
    const float* dil3_pw  = (const float*)d_in[18];
    const float* dil5_dw  = (const float*)d_in[19];
    const float* dil5_pw  = (const float*)d_in[20];
    const float* w_1x7    = (const float*)d_in[21];  // (128,128,1,7)
    const float* w_7x1    = (const float*)d_in[22];  // (128,128,7,1)
    float* out = (float*)d_out;

    // CRITICAL FIX: resolve real device addresses of __device__ scratch globals.
    // (Passing the symbol name from host code passes the host shadow address,
    // which on GB300 (ATS) is silently dereferenceable -> garbage, no fault.)
    float *t_xtemp, *t_1, *t_2;
    { void* p;
      cudaGetSymbolAddress(&p, g_xtemp); t_xtemp = (float*)p;
      cudaGetSymbolAddress(&p, g_t1);    t_1     = (float*)p;
      cudaGetSymbolAddress(&p, g_t2);    t_2     = (float*)p; }

    const int GSEL = NSEL / 256;   // 32768
    const int GALL = NALL / 256;   // 131072
    dim3 gconv(2, 8, B);           // 64co x 4y tiles

    // attention + channel select
    pool_reduce_kernel<<<B*C, 128>>>(x);
    attention_kernel<<<B, 128>>>(w_fc1, wall, w_fc2);
    slist_kernel<<<1, C>>>();
    topk_kernel<<<1, C>>>();
    scale_kernel<<<GALL, 256>>>(x, out);
    gather_kernel<<<GSEL, 256>>>(out);

    // branch 1: bn(maxpool3)  (init acc)
    pool3_kernel<true><<<GSEL, 256>>>(t_xtemp, t_1);
    bn_stats_kernel<<<CP, 256>>>(t_1);
    acc_kernel<<<GSEL, 256>>>(t_1, weights, 1, 1, nullptr, 0, 1);
    // branch 2: bn(avgpool3)  + branch 3: identity (folded as extra)
    pool3_kernel<false><<<GSEL, 256>>>(t_xtemp, t_1);
    bn_stats_kernel<<<CP, 256>>>(t_1);
    acc_kernel<<<GSEL, 256>>>(t_1, weights, 2, 1, t_xtemp, 3, 0);

    // sep convs (k=3,5,7) -> weights[4],[5],[6]
    const float* dws[3][2] = {{sep3_dw1, sep3_dw2}, {sep5_dw1, sep5_dw2}, {sep7_dw1, sep7_dw2}};
    const float* pws[3][2] = {{sep3_pw1, sep3_pw2}, {sep5_pw1, sep5_pw2}, {sep7_pw1, sep7_pw2}};
    const int ks[3] = {3, 5, 7};
    for (int s = 0; s < 3; s++) {
        int k = ks[s], p = k / 2;
        dw_conv_kernel<<<GSEL, 256>>>(t_xtemp, t_1, dws[s][0], k, 1, p, 1);   // relu in
        dense_conv_kernel<1,1,0><<<gconv, 256>>>(t_1, t_2, pws[s][0]);
        bn_stats_kernel<<<CP, 256>>>(t_2);
        dw_conv_kernel<<<GSEL, 256>>>(t_2, t_1, dws[s][1], k, 1, p, 2);      // bn+relu in
        dense_conv_kernel<1,1,0><<<gconv, 256>>>(t_1, t_2, pws[s][1]);
        bn_stats_kernel<<<CP, 256>>>(t_2);
        acc_kernel<<<GSEL, 256>>>(t_2, weights, 4 + s, 1, nullptr, 0, 0);
    }

    // dilated convs: (k=3,pad=2) w[7], (k=5,pad=4) w[8]
    dw_conv_kernel<<<GSEL, 256>>>(t_xtemp, t_1, dil3_dw, 3, 2, 2, 1);
    dense_conv_kernel<1,1,0><<<gconv, 256>>>(t_1, t_2, dil3_pw);
    bn_stats_kernel<<<CP, 256>>>(t_2);
    acc_kernel<<<GSEL, 256>>>(t_2, weights, 7, 1, nullptr, 0, 0);

    dw_conv_kernel<<<GSEL, 256>>>(t_xtemp, t_1, dil5_dw, 5, 2, 4, 1);
    dense_conv_kernel<1,1,0><<<gconv, 256>>>(t_1, t_2, dil5_pw);
    bn_stats_kernel<<<CP, 256>>>(t_2);
    acc_kernel<<<GSEL, 256>>>(t_2, weights, 8, 1, nullptr, 0, 0);

    // 1x7 then 7x1 conv -> w[9]
    dense_conv_kernel<1,7,1><<<gconv, 256>>>(t_xtemp, t_1, w_1x7);
    dense_conv_kernel<7,1,0><<<gconv, 256>>>(t_1, t_2, w_7x1);
    bn_stats_kernel<<<CP, 256>>>(t_2);
    acc_kernel<<<GSEL, 256>>>(t_2, weights, 9, 1, nullptr, 0, 0);

    // scatter result into selected channels
    scatter_kernel<<<GSEL, 256>>>(out);
}

// round 6
// speedup vs baseline: 1.8306x; 1.8306x over previous
#include <cuda_runtime.h>
#include <cuda_bf16.h>
#include <math.h>

// Problem constants
#define B   64
#define C   512
#define CP  128
#define HH  32
#define WW  32
#define HW  1024
#define NSEL (B*CP*HW)       // 8388608
#define NALL (B*C*HW)        // 33554432
#define NSLOT 11

// ---------------- scratch (device globals; no allocs allowed) ----------------
__device__ float g_pooled[B*2*C];
__device__ float g_ca[B*C];
__device__ float g_slist[C];
__device__ int   g_idx[CP];
__device__ float g_xtemp[NSEL];
__device__ float g_t1[NSEL];
__device__ float g_t2[NSEL];
__device__ float g_bmax[NSEL];
__device__ float g_bavg[NSEL];
__device__ float g_s3[NSEL];
__device__ float g_s5[NSEL];
__device__ float g_s7[NSEL];
__device__ float g_d3[NSEL];
__device__ float g_d5[NSEL];
__device__ float g_c7[NSEL];
__device__ double g_ssum [NSLOT*CP];
__device__ double g_ssum2[NSLOT*CP];
__device__ float  g_meanv[NSLOT*CP];
__device__ float  g_rstdv[NSLOT*CP];

// slots: 0 max, 1 avg, 2 sep3mid, 3 sep3fin, 4 sep5mid, 5 sep5fin,
//        6 sep7mid, 7 sep7fin, 8 dil3, 9 dil5, 10 c7

// ---------------- f32x2 helpers ----------------
__device__ __forceinline__ unsigned long long pack2(float a, float b){
    unsigned long long r; asm("mov.b64 %0,{%1,%2};":"=l"(r):"f"(a),"f"(b)); return r;
}
__device__ __forceinline__ void unpack2(unsigned long long v, float&a, float&b){
    asm("mov.b64 {%0,%1},%2;":"=f"(a),"=f"(b):"l"(v));
}
__device__ __forceinline__ void ffma2(unsigned long long&d, unsigned long long a, unsigned long long b){
    asm("fma.rn.f32x2 %0,%1,%2,%0;":"+l"(d):"l"(a),"l"(b));
}

// ---------------- 0. zero stats ----------------
__global__ void zero_stats_kernel(){
    int i = blockIdx.x*256 + threadIdx.x;
    if (i < NSLOT*CP){ g_ssum[i]=0.0; g_ssum2[i]=0.0; }
}

// ---------------- finalize stats (slot>=0: that slot; slot<0: blockIdx = slot)
__global__ void finalize_kernel(int slot){
    int s = (slot < 0) ? blockIdx.x : slot;
    int c = threadIdx.x;                 // 128
    double su = g_ssum[s*CP+c], sq = g_ssum2[s*CP+c];
    double m  = su * (1.0/65536.0);
    double var = sq * (1.0/65536.0) - m*m;
    g_meanv[s*CP+c] = (float)m;
    g_rstdv[s*CP+c] = (float)rsqrt(var + 1e-5);
}

// ---------------- 1. per-(b,c) avg + max over HW ----------------
__global__ void pool_reduce_kernel(const float* __restrict__ x) {
    int bc = blockIdx.x;
    const float* p = x + (size_t)bc * HW;
    int tid = threadIdx.x;               // 128
    float s = 0.f, m = -INFINITY;
    for (int i = tid; i < HW; i += 128) { float v = p[i]; s += v; m = fmaxf(m, v); }
    __shared__ float ss[128], sm[128];
    ss[tid] = s; sm[tid] = m; __syncthreads();
    for (int st = 64; st > 0; st >>= 1) {
        if (tid < st) { ss[tid] += ss[tid+st]; sm[tid] = fmaxf(sm[tid], sm[tid+st]); }
        __syncthreads();
    }
    if (tid == 0) {
        int b = bc >> 9, c = bc & 511;
        g_pooled[b*2*C + c]     = ss[0] * (1.f/1024.f);
        g_pooled[b*2*C + C + c] = sm[0];
    }
}

// ---------------- 2. channel attention MLP ----------------
__global__ void attention_kernel(const float* __restrict__ fc1,
                                 const float* __restrict__ wa,
                                 const float* __restrict__ fc2) {
    int b = blockIdx.x, tid = threadIdx.x;   // 128
    __shared__ float red[128];
    __shared__ float s_y[10], s_A[100], s_y2[10];
    const float* pr = g_pooled + b*2*C;
    for (int j = 0; j < 10; j++) {
        float local = 0.f;
        for (int i = tid; i < 2*C; i += 128) local += pr[i] * fc1[j*2*C + i];
        red[tid] = local; __syncthreads();
        for (int st = 64; st > 0; st >>= 1) { if (tid < st) red[tid] += red[tid+st]; __syncthreads(); }
        if (tid == 0) s_y[j] = red[0];
        __syncthreads();
    }
    if (tid < 100) {
        int j = tid / 10, k = tid % 10;
        float a = 0.f;
        for (int m = 0; m < 14; m++) a += wa[m*10 + j] * wa[m*10 + k];
        s_A[tid] = a;
    }
    __syncthreads();
    if (tid < 10) {
        float v = 0.f;
        for (int k = 0; k < 10; k++) v += s_y[k] * s_A[tid*10 + k];
        s_y2[tid] = fmaxf(v, 0.f);
    }
    __syncthreads();
    for (int c = tid; c < C; c += 128) {
        float v = 0.f;
        for (int j = 0; j < 10; j++) v += s_y2[j] * fc2[c*10 + j];
        g_ca[b*C + c] = 1.f / (1.f + expf(-v));
    }
}

// ---------------- 3. slist + exact lax.top_k ordering ----------------
__global__ void slist_kernel() {
    int c = threadIdx.x;                     // 512
    float s = 0.f;
    for (int b = 0; b < B; b++) s += g_ca[b*C + c];
    g_slist[c] = s;
}
__global__ void topk_kernel() {
    __shared__ float v[C];
    int tid = threadIdx.x;                   // 512
    v[tid] = g_slist[tid]; __syncthreads();
    float mv = v[tid];
    int rank = 0;
    for (int i = 0; i < C; i++) {
        float o = v[i];
        rank += (o > mv) || (o == mv && i < tid);
    }
    if (rank < CP) g_idx[rank] = tid;
}

// ---------------- 4. scale x by ca into d_out (float4) ----------------
__global__ void scale4_kernel(const float* __restrict__ x, float* __restrict__ out) {
    int n4 = blockIdx.x * 256 + threadIdx.x;   // < NALL/4
    int n = n4 << 2;
    float ca = g_ca[n >> 10];
    float4 v = *(const float4*)&x[n];
    v.x *= ca; v.y *= ca; v.z *= ca; v.w *= ca;
    *(float4*)&out[n] = v;
}

// ---------------- 5. gather xtemp = (x*ca)[:, idx] (float4) ----------------
__global__ void gather4_kernel(const float* __restrict__ x) {
    int n4 = blockIdx.x * 256 + threadIdx.x;   // < NSEL/4
    int n = n4 << 2;
    int b = n >> 17, p = (n >> 10) & 127, hw = n & 1023;
    int cs = g_idx[p];
    float ca = g_ca[b*C + cs];
    float4 v = *(const float4*)&x[(((size_t)b*C + cs) << 10) + hw];
    v.x *= ca; v.y *= ca; v.z *= ca; v.w *= ca;
    *(float4*)&g_xtemp[n] = v;
}

// ---------------- 6. 3x3 max/avg pool + fused stats ----------------
template<bool ISMAX>
__global__ void pool3_kernel(const float* __restrict__ in, float* __restrict__ out, int slot) {
    int n = blockIdx.x * 256 + threadIdx.x;  // < NSEL; block covers one (b,c) quarter-page
    int hw = n & 1023, y = hw >> 5, x = hw & 31;
    const float* ip = in + ((size_t)(n >> 10) << 10);
    float m = -INFINITY, s = 0.f; int cnt = 0;
    #pragma unroll
    for (int dy = -1; dy <= 1; dy++) {
        int yy = y + dy; if (yy < 0 || yy >= HH) continue;
        #pragma unroll
        for (int dx = -1; dx <= 1; dx++) {
            int xx = x + dx; if (xx < 0 || xx >= WW) continue;
            float v = ip[yy*WW + xx];
            if (ISMAX) m = fmaxf(m, v); else { s += v; cnt++; }
        }
    }
    float val = ISMAX ? m : s / (float)cnt;
    out[n] = val;
    __shared__ float rs[256], rs2[256];
    int tid = threadIdx.x;
    rs[tid] = val; rs2[tid] = val*val; __syncthreads();
    for (int st = 128; st > 0; st >>= 1) {
        if (tid < st) { rs[tid] += rs[tid+st]; rs2[tid] += rs2[tid+st]; }
        __syncthreads();
    }
    if (tid == 0) {
        int c = (n >> 10) & 127;
        atomicAdd(&g_ssum [slot*CP + c], (double)rs[0]);
        atomicAdd(&g_ssum2[slot*CP + c], (double)rs2[0]);
    }
}

// ---------------- 7. depthwise conv, smem image tile, 4-wide reuse ------------
// TRANS: 0 none, 1 relu, 2 bn(islot)+relu
template<int K, int DIL, int TRANS>
__global__ void __launch_bounds__(256) dw_conv_kernel(const float* __restrict__ in,
                                                      float* __restrict__ out,
                                                      const float* __restrict__ w,
                                                      int islot) {
    constexpr int P  = (DIL==1) ? (K/2) : (K-1);
    constexpr int SW = 32 + 2*P;
    constexpr int SWP = SW + 1;       // odd stride -> conflict-free
    constexpr int SPAN = 4 + (K-1)*DIL;
    __shared__ float s[SW][SWP];
    int bc = blockIdx.x;              // b*CP + c
    int c = bc & 127;
    int tid = threadIdx.x;
    float mean = 0.f, rstd = 1.f;
    if (TRANS == 2) { mean = g_meanv[islot*CP + c]; rstd = g_rstdv[islot*CP + c]; }
    const float* ip = in + ((size_t)bc << 10);
    for (int i = tid; i < SW*SW; i += 256) {
        int r = i / SW, q = i - r*SW;
        int y = r - P, x = q - P;
        float v = 0.f;
        if (y >= 0 && y < 32 && x >= 0 && x < 32) {
            v = ip[y*32 + x];
            if (TRANS == 1) v = fmaxf(v, 0.f);
            else if (TRANS == 2) v = fmaxf((v - mean)*rstd, 0.f);
        }
        s[r][q] = v;
    }
    float wr[K][K];
    #pragma unroll
    for (int i = 0; i < K; i++)
        #pragma unroll
        for (int j = 0; j < K; j++) wr[i][j] = w[(c*K + i)*K + j];
    __syncthreads();
    int y = tid >> 3, x0 = (tid & 7) * 4;
    float acc[4] = {0.f, 0.f, 0.f, 0.f};
    #pragma unroll
    for (int i = 0; i < K; i++) {
        float r[SPAN];
        #pragma unroll
        for (int q = 0; q < SPAN; q++) r[q] = s[y + i*DIL][x0 + q];
        #pragma unroll
        for (int j = 0; j < K; j++)
            #pragma unroll
            for (int t = 0; t < 4; t++) acc[t] = fmaf(wr[i][j], r[j*DIL + t], acc[t]);
    }
    *(float4*)&out[((size_t)bc << 10) + y*32 + x0] = make_float4(acc[0],acc[1],acc[2],acc[3]);
}

// ---------------- 8. pointwise conv 128->128, f32x2, fused stats --------------
// block: 64co x 8y x 32x; threads 256: xp=tid&15 (x pair), cg=tid>>4 (4-co group)
__global__ void __launch_bounds__(256) pw_conv_kernel(const float* __restrict__ in,
                                                      float* __restrict__ out,
                                                      const float* __restrict__ w,
                                                      int oslot) {
    __shared__ __align__(16) float s_in[16][8][32];
    __shared__ float s_w[64][16];
    int tid = threadIdx.x;
    int co0 = blockIdx.x * 64, y0 = blockIdx.y * 8, b = blockIdx.z;
    int xp = tid & 15, cg = tid >> 4;
    unsigned long long acc[4][8];
    #pragma unroll
    for (int j = 0; j < 4; j++)
        #pragma unroll
        for (int y = 0; y < 8; y++) acc[j][y] = 0ull;

    for (int cc = 0; cc < CP; cc += 16) {
        { int co = tid >> 2, q = tid & 3;
          float4 v = *(const float4*)&w[(size_t)(co0+co)*CP + cc + q*4];
          s_w[co][q*4+0]=v.x; s_w[co][q*4+1]=v.y; s_w[co][q*4+2]=v.z; s_w[co][q*4+3]=v.w; }
        { int r = tid >> 1, h = tid & 1;
          int ci = r >> 3, y = r & 7;
          const float4* src = (const float4*)&in[(((size_t)b*CP + cc+ci)*HH + y0+y)*WW + h*16];
          float4* dst = (float4*)&s_in[ci][y][h*16];
          dst[0]=src[0]; dst[1]=src[1]; dst[2]=src[2]; dst[3]=src[3]; }
        __syncthreads();
        #pragma unroll
        for (int ci = 0; ci < 16; ci++) {
            unsigned long long iv[8];
            #pragma unroll
            for (int y = 0; y < 8; y++) iv[y] = *(const unsigned long long*)&s_in[ci][y][2*xp];
            #pragma unroll
            for (int j = 0; j < 4; j++) {
                float wv = s_w[cg*4 + j][ci];
                unsigned long long wv2 = pack2(wv, wv);
                #pragma unroll
                for (int y = 0; y < 8; y++) ffma2(acc[j][y], wv2, iv[y]);
            }
        }
        __syncthreads();
    }
    #pragma unroll
    for (int j = 0; j < 4; j++) {
        int co = co0 + cg*4 + j;
        float s = 0.f, s2 = 0.f;
        #pragma unroll
        for (int y = 0; y < 8; y++) {
            float v0, v1; unpack2(acc[j][y], v0, v1);
            float2 st = make_float2(v0, v1);
            *(float2*)&out[(((size_t)b*CP + co)*HH + y0+y)*WW + 2*xp] = st;
            s += v0 + v1; s2 += v0*v0 + v1*v1;
        }
        #pragma unroll
        for (int o = 1; o < 16; o <<= 1) {
            s  += __shfl_xor_sync(0xffffffffu, s,  o);
            s2 += __shfl_xor_sync(0xffffffffu, s2, o);
        }
        if (xp == 0 && oslot >= 0) {
            atomicAdd(&g_ssum [oslot*CP + co], (double)s);
            atomicAdd(&g_ssum2[oslot*CP + co], (double)s2);
        }
    }
}

// ---------------- 9. 7x1 conv (KH=7, pad 3), f32x2 x-pair, fused stats --------
__global__ void __launch_bounds__(256) conv7x1_kernel(const float* __restrict__ in,
                                                      float* __restrict__ out,
                                                      const float* __restrict__ w,
                                                      int oslot) {
    __shared__ __align__(16) float s_in[16][14][32];
    __shared__ float s_w[64][16][7];
    int tid = threadIdx.x;
    int co0 = blockIdx.x * 64, y0 = blockIdx.y * 8, b = blockIdx.z;
    int xp = tid & 15, cg = tid >> 4;
    unsigned long long acc[4][8];
    #pragma unroll
    for (int j = 0; j < 4; j++)
        #pragma unroll
        for (int y = 0; y < 8; y++) acc[j][y] = 0ull;

    for (int cc = 0; cc < CP; cc += 16) {
        for (int i = tid; i < 16*14*32; i += 256) {
            int ci = i / 448, rem = i - ci*448;
            int r = rem >> 5, q = rem & 31;
            int y = y0 + r - 3;
            float v = 0.f;
            if (y >= 0 && y < HH) v = in[(((size_t)b*CP + cc+ci)*HH + y)*WW + q];
            s_in[ci][r][q] = v;
        }
        for (int i = tid; i < 64*16*7; i += 256) {
            int co = i / 112, rem = i - co*112;
            int ci = rem / 7, kh = rem - ci*7;
            s_w[co][ci][kh] = w[((size_t)(co0+co)*CP + cc+ci)*7 + kh];
        }
        __syncthreads();
        #pragma unroll 2
        for (int ci = 0; ci < 16; ci++) {
            unsigned long long iv[14];
            #pragma unroll
            for (int r = 0; r < 14; r++) iv[r] = *(const unsigned long long*)&s_in[ci][r][2*xp];
            #pragma unroll
            for (int j = 0; j < 4; j++) {
                #pragma unroll
                for (int kh = 0; kh < 7; kh++) {
                    float wv = s_w[cg*4 + j][ci][kh];
                    unsigned long long wv2 = pack2(wv, wv);
                    #pragma unroll
                    for (int y = 0; y < 8; y++) ffma2(acc[j][y], wv2, iv[y + kh]);
                }
            }
        }
        __syncthreads();
    }
    #pragma unroll
    for (int j = 0; j < 4; j++) {
        int co = co0 + cg*4 + j;
        float s = 0.f, s2 = 0.f;
        #pragma unroll
        for (int y = 0; y < 8; y++) {
            float v0, v1; unpack2(acc[j][y], v0, v1);
            *(float2*)&out[(((size_t)b*CP + co)*HH + y0+y)*WW + 2*xp] = make_float2(v0, v1);
            s += v0 + v1; s2 += v0*v0 + v1*v1;
        }
        #pragma unroll
        for (int o = 1; o < 16; o <<= 1) {
            s  += __shfl_xor_sync(0xffffffffu, s,  o);
            s2 += __shfl_xor_sync(0xffffffffu, s2, o);
        }
        if (xp == 0 && oslot >= 0) {
            atomicAdd(&g_ssum [oslot*CP + co], (double)s);
            atomicAdd(&g_ssum2[oslot*CP + co], (double)s2);
        }
    }
}

// ---------------- 10. 1x7 conv (KW=7, pad 3), relu-in, f32x2 y-pair -----------
// threads: xc=tid&31, cg=tid>>5 (8-co group); acc[8co][4 y-pairs]
__global__ void __launch_bounds__(256) conv1x7_kernel(const float* __restrict__ in,
                                                      float* __restrict__ out,
                                                      const float* __restrict__ w) {
    __shared__ float s_in[16][8][38];
    __shared__ float s_w[64][16][7];
    int tid = threadIdx.x;
    int co0 = blockIdx.x * 64, y0 = blockIdx.y * 8, b = blockIdx.z;
    int xc = tid & 31, cg = tid >> 5;
    unsigned long long acc[8][4];
    #pragma unroll
    for (int j = 0; j < 8; j++)
        #pragma unroll
        for (int yp = 0; yp < 4; yp++) acc[j][yp] = 0ull;

    for (int cc = 0; cc < CP; cc += 16) {
        for (int i = tid; i < 16*8*38; i += 256) {
            int ci = i / 304, rem = i - ci*304;
            int y = rem / 38, q = rem - y*38;
            int xx = q - 3;
            float v = 0.f;
            if (xx >= 0 && xx < WW) {
                v = in[(((size_t)b*CP + cc+ci)*HH + y0+y)*WW + xx];
                v = fmaxf(v, 0.f);     // relu on input
            }
            s_in[ci][y][q] = v;
        }
        for (int i = tid; i < 64*16*7; i += 256) {
            int co = i / 112, rem = i - co*112;
            int ci = rem / 7, kw = rem - ci*7;
            s_w[co][ci][kw] = w[((size_t)(co0+co)*CP + cc+ci)*7 + kw];
        }
        __syncthreads();
        #pragma unroll 2
        for (int ci = 0; ci < 16; ci++) {
            #pragma unroll
            for (int kw = 0; kw < 7; kw++) {
                unsigned long long iv[4];
                #pragma unroll
                for (int yp = 0; yp < 4; yp++)
                    iv[yp] = pack2(s_in[ci][2*yp][xc+kw], s_in[ci][2*yp+1][xc+kw]);
                #pragma unroll
                for (int j = 0; j < 8; j++) {
                    float wv = s_w[cg*8 + j][ci][kw];
                    unsigned long long wv2 = pack2(wv, wv);
                    #pragma unroll
                    for (int yp = 0; yp < 4; yp++) ffma2(acc[j][yp], wv2, iv[yp]);
                }
            }
        }
        __syncthreads();
    }
    #pragma unroll
    for (int j = 0; j < 8; j++) {
        int co = co0 + cg*8 + j;
        #pragma unroll
        for (int yp = 0; yp < 4; yp++) {
            float v0, v1; unpack2(acc[j][yp], v0, v1);
            out[(((size_t)b*CP + co)*HH + y0+2*yp  )*WW + xc] = v0;
            out[(((size_t)b*CP + co)*HH + y0+2*yp+1)*WW + xc] = v1;
        }
    }
}

// ---------------- 11. final combine + scatter (float4) ------------------------
__global__ void combine_kernel(const float* __restrict__ wv, float* __restrict__ out) {
    int n4 = blockIdx.x * 256 + threadIdx.x;   // < NSEL/4; block covers one (b,p) page
    int n = n4 << 2;
    int b = n >> 17, p = (n >> 10) & 127, hw = n & 1023;
    float m0 = g_meanv[0*CP+p],  r0 = g_rstdv[0*CP+p];
    float m1 = g_meanv[1*CP+p],  r1 = g_rstdv[1*CP+p];
    float m3 = g_meanv[3*CP+p],  r3 = g_rstdv[3*CP+p];
    float m5 = g_meanv[5*CP+p],  r5 = g_rstdv[5*CP+p];
    float m7 = g_meanv[7*CP+p],  r7 = g_rstdv[7*CP+p];
    float m8 = g_meanv[8*CP+p],  r8 = g_rstdv[8*CP+p];
    float m9 = g_meanv[9*CP+p],  r9 = g_rstdv[9*CP+p];
    float mA = g_meanv[10*CP+p], rA = g_rstdv[10*CP+p];
    float w1=wv[1],w2=wv[2],w3=wv[3],w4=wv[4],w5=wv[5],w6=wv[6],w7=wv[7],w8=wv[8],w9=wv[9];
    float a[4] = {0.f,0.f,0.f,0.f};
    {
        float4 v = *(const float4*)&g_bmax[n]; const float* q=(const float*)&v;
        #pragma unroll
        for (int t=0;t<4;t++) a[t] += w1*(q[t]-m0)*r0;
    }
    {
        float4 v = *(const float4*)&g_bavg[n]; const float* q=(const float*)&v;
        #pragma unroll
        for (int t=0;t<4;t++) a[t] += w2*(q[t]-m1)*r1;
    }
    {
        float4 v = *(const float4*)&g_xtemp[n]; const float* q=(const float*)&v;
        #pragma unroll
        for (int t=0;t<4;t++) a[t] += w3*q[t];
    }
    {
        float4 v = *(const float4*)&g_s3[n]; const float* q=(const float*)&v;
        #pragma unroll
        for (int t=0;t<4;t++) a[t] += w4*(q[t]-m3)*r3;
    }
    {
        float4 v = *(const float4*)&g_s5[n]; const float* q=(const float*)&v;
        #pragma unroll
        for (int t=0;t<4;t++) a[t] += w5*(q[t]-m5)*r5;
    }
    {
        float4 v = *(const float4*)&g_s7[n]; const float* q=(const float*)&v;
        #pragma unroll
        for (int t=0;t<4;t++) a[t] += w6*(q[t]-m7)*r7;
    }
    {
        float4 v = *(const float4*)&g_d3[n]; const float* q=(const float*)&v;
        #pragma unroll
        for (int t=0;t<4;t++) a[t] += w7*(q[t]-m8)*r8;
    }
    {
        float4 v = *(const float4*)&g_d5[n]; const float* q=(const float*)&v;
        #pragma unroll
        for (int t=0;t<4;t++) a[t] += w8*(q[t]-m9)*r9;
    }
    {
        float4 v = *(const float4*)&g_c7[n]; const float* q=(const float*)&v;
        #pragma unroll
        for (int t=0;t<4;t++) a[t] += w9*(q[t]-mA)*rA;
    }
    int cs = g_idx[p];
    *(float4*)&out[(((size_t)b*C + cs) << 10) + hw] = make_float4(a[0],a[1],a[2],a[3]);
}

// =============================================================================
extern "C" void kernel_launch(void* const* d_in, const int* in_sizes, int n_in,
                              void* d_out, int out_size) {
    const float* x        = (const float*)d_in[0];
    const float* weights  = (const float*)d_in[1];
    const float* wall     = (const float*)d_in[2];
    const float* w_fc1    = (const float*)d_in[3];
    const float* w_fc2    = (const float*)d_in[4];
    const float* sep3_dw1 = (const float*)d_in[5];
    const float* sep3_pw1 = (const float*)d_in[6];
    const float* sep3_dw2 = (const float*)d_in[7];
    const float* sep3_pw2 = (const float*)d_in[8];
    const float* sep5_dw1 = (const float*)d_in[9];
    const float* sep5_pw1 = (const float*)d_in[10];
    const float* sep5_dw2 = (const float*)d_in[11];
    const float* sep5_pw2 = (const float*)d_in[12];
    const float* sep7_dw1 = (const float*)d_in[13];
    const float* sep7_pw1 = (const float*)d_in[14];
    const float* sep7_dw2 = (const float*)d_in[15];
    const float* sep7_pw2 = (const float*)d_in[16];
    const float* dil3_dw  = (const float*)d_in[17];
    const float* dil3_pw  = (const float*)d_in[18];
    const float* dil5_dw  = (const float*)d_in[19];
    const float* dil5_pw  = (const float*)d_in[20];
    const float* w_1x7    = (const float*)d_in[21];
    const float* w_7x1    = (const float*)d_in[22];
    float* out = (float*)d_out;

    // Resolve REAL device addresses of scratch globals (host shadow symbols are
    // ATS-dereferenceable garbage on GB300 — R2 lesson).
    float *t_xtemp,*t_1,*t_2,*t_bmax,*t_bavg,*t_s3,*t_s5,*t_s7,*t_d3,*t_d5,*t_c7;
    { void* p;
      cudaGetSymbolAddress(&p, g_xtemp); t_xtemp=(float*)p;
      cudaGetSymbolAddress(&p, g_t1);    t_1    =(float*)p;
      cudaGetSymbolAddress(&p, g_t2);    t_2    =(float*)p;
      cudaGetSymbolAddress(&p, g_bmax);  t_bmax =(float*)p;
      cudaGetSymbolAddress(&p, g_bavg);  t_bavg =(float*)p;
      cudaGetSymbolAddress(&p, g_s3);    t_s3   =(float*)p;
      cudaGetSymbolAddress(&p, g_s5);    t_s5   =(float*)p;
      cudaGetSymbolAddress(&p, g_s7);    t_s7   =(float*)p;
      cudaGetSymbolAddress(&p, g_d3);    t_d3   =(float*)p;
      cudaGetSymbolAddress(&p, g_d5);    t_d5   =(float*)p;
      cudaGetSymbolAddress(&p, g_c7);    t_c7   =(float*)p; }

    const int GSEL  = NSEL / 256;    // 32768
    const int GSEL4 = NSEL / 1024;   // 8192
    const int GALL4 = NALL / 1024;   // 32768
    dim3 gconv(2, 4, B);             // 64co x 8y tiles
    const int GDW = B * CP;          // 8192

    zero_stats_kernel<<<(NSLOT*CP + 255)/256, 256>>>();

    // attention + channel select
    pool_reduce_kernel<<<B*C, 128>>>(x);
    attention_kernel<<<B, 128>>>(w_fc1, wall, w_fc2);
    slist_kernel<<<1, C>>>();
    topk_kernel<<<1, C>>>();
    scale4_kernel<<<GALL4, 256>>>(x, out);
    gather4_kernel<<<GSEL4, 256>>>(x);

    // pool branches (stats fused)
    pool3_kernel<true ><<<GSEL, 256>>>(t_xtemp, t_bmax, 0);
    pool3_kernel<false><<<GSEL, 256>>>(t_xtemp, t_bavg, 1);

    // sep3: slots mid=2, fin=3
    dw_conv_kernel<3,1,1><<<GDW, 256>>>(t_xtemp, t_1, sep3_dw1, 0);
    pw_conv_kernel<<<gconv, 256>>>(t_1, t_2, sep3_pw1, 2);
    finalize_kernel<<<1, 128>>>(2);
    dw_conv_kernel<3,1,2><<<GDW, 256>>>(t_2, t_1, sep3_dw2, 2);
    pw_conv_kernel<<<gconv, 256>>>(t_1, t_s3, sep3_pw2, 3);

    // sep5: slots 4,5
    dw_conv_kernel<5,1,1><<<GDW, 256>>>(t_xtemp, t_1, sep5_dw1, 0);
    pw_conv_kernel<<<gconv, 256>>>(t_1, t_2, sep5_pw1, 4);
    finalize_kernel<<<1, 128>>>(4);
    dw_conv_kernel<5,1,2><<<GDW, 256>>>(t_2, t_1, sep5_dw2, 4);
    pw_conv_kernel<<<gconv, 256>>>(t_1, t_s5, sep5_pw2, 5);

    // sep7: slots 6,7
    dw_conv_kernel<7,1,1><<<GDW, 256>>>(t_xtemp, t_1, sep7_dw1, 0);
    pw_conv_kernel<<<gconv, 256>>>(t_1, t_2, sep7_pw1, 6);
    finalize_kernel<<<1, 128>>>(6);
    dw_conv_kernel<7,1,2><<<GDW, 256>>>(t_2, t_1, sep7_dw2, 6);
    pw_conv_kernel<<<gconv, 256>>>(t_1, t_s7, sep7_pw2, 7);

    // dil3 (k=3, dil=2, pad=2): slot 8
    dw_conv_kernel<3,2,1><<<GDW, 256>>>(t_xtemp, t_1, dil3_dw, 0);
    pw_conv_kernel<<<gconv, 256>>>(t_1, t_d3, dil3_pw, 8);

    // dil5 (k=5, dil=2, pad=4): slot 9
    dw_conv_kernel<5,2,1><<<GDW, 256>>>(t_xtemp, t_1, dil5_dw, 0);
    pw_conv_kernel<<<gconv, 256>>>(t_1, t_d5, dil5_pw, 9);

    // 1x7 -> 7x1: slot 10
    conv1x7_kernel<<<gconv, 256>>>(t_xtemp, t_1, w_1x7);
    conv7x1_kernel<<<gconv, 256>>>(t_1, t_c7, w_7x1, 10);

    // finalize everything, combine, scatter
    finalize_kernel<<<NSLOT, 128>>>(-1);
    combine_kernel<<<GSEL4, 256>>>(weights, out);
}

// round 7
// speedup vs baseline: 2.1019x; 1.1482x over previous
#include <cuda_runtime.h>
#include <cuda_bf16.h>
#include <math.h>

#define B   64
#define C   512
#define CP  128
#define HH  32
#define WW  32
#define HW  1024
#define NSEL (B*CP*HW)       // 8388608
#define NALL (B*C*HW)        // 33554432
#define NSLOT 11

// ---------------- scratch (device globals; no allocs allowed) ----------------
__device__ float g_ca[B*C];
__device__ int   g_idx[CP];
__device__ float g_xtemp[NSEL];
__device__ float g_t1[NSEL];
__device__ float g_t2[NSEL];
__device__ float g_bmax[NSEL];
__device__ float g_bavg[NSEL];
__device__ float g_s3[NSEL];
__device__ float g_s5[NSEL];
__device__ float g_s7[NSEL];
__device__ float g_d3[NSEL];
__device__ float g_d5[NSEL];
__device__ float g_c7[NSEL];
__device__ double g_ssum [NSLOT*CP];
__device__ double g_ssum2[NSLOT*CP];
__device__ float  g_meanv[NSLOT*CP];
__device__ float  g_rstdv[NSLOT*CP];

// slots: 0 max, 1 avg, 2 sep3mid, 3 sep3fin, 4 sep5mid, 5 sep5fin,
//        6 sep7mid, 7 sep7fin, 8 dil3, 9 dil5, 10 c7

typedef unsigned long long ull;
__device__ __forceinline__ ull pack2(float a, float b){
    ull r; asm("mov.b64 %0,{%1,%2};":"=l"(r):"f"(a),"f"(b)); return r;
}
__device__ __forceinline__ void unpack2(ull v, float&a, float&b){
    asm("mov.b64 {%0,%1},%2;":"=f"(a),"=f"(b):"l"(v));
}
__device__ __forceinline__ void ffma2(ull&d, ull a, ull b){
    asm("fma.rn.f32x2 %0,%1,%2,%0;":"+l"(d):"l"(a),"l"(b));
}

// ---------------- 0. fused global pooling + attention MLP (+ stats zero) -----
__global__ void __launch_bounds__(512) attn_fused_kernel(
        const float* __restrict__ x, const float* __restrict__ fc1,
        const float* __restrict__ wa, const float* __restrict__ fc2) {
    int b = blockIdx.x, tid = threadIdx.x;     // 512 threads
    __shared__ float pooled[1024];             // [avg 512 | max 512]
    __shared__ float red[16];
    __shared__ float s_y[10], s_A[100], s_y2[10];
    if (b == 0) {
        for (int i = tid; i < NSLOT*CP; i += 512) { g_ssum[i] = 0.0; g_ssum2[i] = 0.0; }
    }
    int w = tid >> 5, l = tid & 31;
    for (int j = 0; j < 32; j++) {
        int c = w*32 + j;
        const float* p = x + ((size_t)(b*C + c) << 10);
        float s = 0.f, m = -INFINITY;
        #pragma unroll 4
        for (int k = 0; k < 32; k++) { float v = p[l + 32*k]; s += v; m = fmaxf(m, v); }
        #pragma unroll
        for (int o = 16; o > 0; o >>= 1) {
            s += __shfl_xor_sync(0xffffffffu, s, o);
            m = fmaxf(m, __shfl_xor_sync(0xffffffffu, m, o));
        }
        if (l == 0) { pooled[c] = s * (1.f/1024.f); pooled[C + c] = m; }
    }
    __syncthreads();
    for (int j = 0; j < 10; j++) {
        float local = pooled[tid] * fc1[j*2*C + tid] + pooled[512 + tid] * fc1[j*2*C + 512 + tid];
        #pragma unroll
        for (int o = 16; o > 0; o >>= 1) local += __shfl_xor_sync(0xffffffffu, local, o);
        if (l == 0) red[w] = local;
        __syncthreads();
        if (tid == 0) { float t = 0.f; for (int q = 0; q < 16; q++) t += red[q]; s_y[j] = t; }
        __syncthreads();
    }
    if (tid < 100) {
        int j = tid / 10, k = tid % 10;
        float a = 0.f;
        for (int m = 0; m < 14; m++) a += wa[m*10 + j] * wa[m*10 + k];
        s_A[tid] = a;
    }
    __syncthreads();
    if (tid < 10) {
        float v = 0.f;
        for (int k = 0; k < 10; k++) v += s_y[k] * s_A[tid*10 + k];
        s_y2[tid] = fmaxf(v, 0.f);
    }
    __syncthreads();
    {
        int c = tid;
        float v = 0.f;
        for (int j = 0; j < 10; j++) v += s_y2[j] * fc2[c*10 + j];
        g_ca[b*C + c] = 1.f / (1.f + expf(-v));
    }
}

// ---------------- 1. slist + exact lax.top_k ordering (merged) ----------------
__global__ void slist_topk_kernel() {
    __shared__ float v[C];
    int c = threadIdx.x;                       // 512
    float s = 0.f;
    for (int b = 0; b < B; b++) s += g_ca[b*C + c];
    v[c] = s; __syncthreads();
    float mv = v[c];
    int rank = 0;
    for (int i = 0; i < C; i++) {
        float o = v[i];
        rank += (o > mv) || (o == mv && i < c);
    }
    if (rank < CP) g_idx[rank] = c;
}

// ---------------- 2. gather xtemp = (x*ca)[:, idx] (float4) ----------------
__global__ void gather4_kernel(const float* __restrict__ x) {
    int n4 = blockIdx.x * 256 + threadIdx.x;   // < NSEL/4
    int n = n4 << 2;
    int b = n >> 17, p = (n >> 10) & 127, hw = n & 1023;
    int cs = g_idx[p];
    float ca = g_ca[b*C + cs];
    float4 v = *(const float4*)&x[(((size_t)b*C + cs) << 10) + hw];
    v.x *= ca; v.y *= ca; v.z *= ca; v.w *= ca;
    *(float4*)&g_xtemp[n] = v;
}

// ---------------- scale x by ca into d_out (float4) ----------------
__global__ void scale4_kernel(const float* __restrict__ x, float* __restrict__ out) {
    int n4 = blockIdx.x * 256 + threadIdx.x;   // < NALL/4
    int n = n4 << 2;
    float ca = g_ca[n >> 10];
    float4 v = *(const float4*)&x[n];
    v.x *= ca; v.y *= ca; v.z *= ca; v.w *= ca;
    *(float4*)&out[n] = v;
}

// ---------------- fused 3x3 max+avg pool + stats (smem tile) ----------------
__global__ void __launch_bounds__(256) pool3f_kernel(const float* __restrict__ in,
                                                     float* __restrict__ omax,
                                                     float* __restrict__ oavg) {
    __shared__ float s[34][35];
    __shared__ float rsm[8][4];
    int bc = blockIdx.x;
    int tid = threadIdx.x;
    const float* ip = in + ((size_t)bc << 10);
    for (int i = tid; i < 34*34; i += 256) {
        int r = i / 34, q = i - r*34;
        int y = r - 1, x = q - 1;
        s[r][q] = (y >= 0 && y < 32 && x >= 0 && x < 32) ? ip[y*32 + x] : 0.f;
    }
    __syncthreads();
    int y = tid >> 3, x0 = (tid & 7) * 4;
    float vmax[4], vavg[4];
    int yl = (y > 0 ? y-1 : 0), yhh = (y < 31 ? y+1 : 31);
    int ch = yhh - yl + 1;
    #pragma unroll
    for (int t = 0; t < 4; t++) {
        int x = x0 + t;
        float m = -INFINITY, sm = 0.f;
        #pragma unroll
        for (int dy = 0; dy < 3; dy++) {
            int yy = y + dy;           // tile coords (y-1+dy)+1
            bool yok = (yy >= 1 && yy <= 32);
            #pragma unroll
            for (int dx = 0; dx < 3; dx++) {
                int xx = x + dx;
                float v = s[yy][xx];
                sm += v;
                if (yok && xx >= 1 && xx <= 32) m = fmaxf(m, v);
            }
        }
        int xl = (x > 0 ? x-1 : 0), xh = (x < 31 ? x+1 : 31);
        int cnt = ch * (xh - xl + 1);
        vmax[t] = m; vavg[t] = sm / (float)cnt;
    }
    size_t base = ((size_t)bc << 10) + y*32 + x0;
    *(float4*)&omax[base] = make_float4(vmax[0],vmax[1],vmax[2],vmax[3]);
    *(float4*)&oavg[base] = make_float4(vavg[0],vavg[1],vavg[2],vavg[3]);
    // stats: both slots
    float sM=0,sM2=0,sA=0,sA2=0;
    #pragma unroll
    for (int t = 0; t < 4; t++) { sM += vmax[t]; sM2 += vmax[t]*vmax[t]; sA += vavg[t]; sA2 += vavg[t]*vavg[t]; }
    #pragma unroll
    for (int o = 16; o > 0; o >>= 1) {
        sM  += __shfl_xor_sync(0xffffffffu, sM,  o);
        sM2 += __shfl_xor_sync(0xffffffffu, sM2, o);
        sA  += __shfl_xor_sync(0xffffffffu, sA,  o);
        sA2 += __shfl_xor_sync(0xffffffffu, sA2, o);
    }
    int w = tid >> 5;
    if ((tid & 31) == 0) { rsm[w][0]=sM; rsm[w][1]=sM2; rsm[w][2]=sA; rsm[w][3]=sA2; }
    __syncthreads();
    if (tid == 0) {
        float a=0,b2=0,c2=0,d2=0;
        for (int q = 0; q < 8; q++) { a+=rsm[q][0]; b2+=rsm[q][1]; c2+=rsm[q][2]; d2+=rsm[q][3]; }
        int c = bc & 127;
        atomicAdd(&g_ssum [0*CP + c], (double)a);
        atomicAdd(&g_ssum2[0*CP + c], (double)b2);
        atomicAdd(&g_ssum [1*CP + c], (double)c2);
        atomicAdd(&g_ssum2[1*CP + c], (double)d2);
    }
}

// ---------------- finalize stats ----------------
__global__ void finalize_kernel() {
    int s = blockIdx.x, c = threadIdx.x;       // 11 x 128
    double su = g_ssum[s*CP+c], sq = g_ssum2[s*CP+c];
    double m  = su * (1.0/65536.0);
    double var = sq * (1.0/65536.0) - m*m;
    g_meanv[s*CP+c] = (float)m;
    g_rstdv[s*CP+c] = (float)rsqrt(var + 1e-5);
}

// ---------------- depthwise conv, smem tile; TRANS: 1 relu, 2 bn+relu --------
template<int K, int DIL, int TRANS>
__global__ void __launch_bounds__(256) dw_conv_kernel(const float* __restrict__ in,
                                                      float* __restrict__ out,
                                                      const float* __restrict__ w,
                                                      int islot) {
    constexpr int P  = (DIL==1) ? (K/2) : (K-1);
    constexpr int SW = 32 + 2*P;
    constexpr int SWP = SW + 1;
    constexpr int SPAN = 4 + (K-1)*DIL;
    __shared__ float s[SW][SWP];
    __shared__ float s_mr[2];
    int bc = blockIdx.x;
    int c = bc & 127;
    int tid = threadIdx.x;
    if (TRANS == 2 && tid == 0) {
        double su = g_ssum[islot*CP + c], sq = g_ssum2[islot*CP + c];
        double m = su * (1.0/65536.0);
        double var = sq * (1.0/65536.0) - m*m;
        s_mr[0] = (float)m; s_mr[1] = (float)rsqrt(var + 1e-5);
    }
    if (TRANS == 2) __syncthreads();
    float mean = 0.f, rstd = 1.f;
    if (TRANS == 2) { mean = s_mr[0]; rstd = s_mr[1]; }
    const float* ip = in + ((size_t)bc << 10);
    for (int i = tid; i < SW*SW; i += 256) {
        int r = i / SW, q = i - r*SW;
        int y = r - P, x = q - P;
        float v = 0.f;
        if (y >= 0 && y < 32 && x >= 0 && x < 32) {
            v = ip[y*32 + x];
            if (TRANS == 1) v = fmaxf(v, 0.f);
            else if (TRANS == 2) v = fmaxf((v - mean)*rstd, 0.f);
        }
        s[r][q] = v;
    }
    float wr[K][K];
    #pragma unroll
    for (int i = 0; i < K; i++)
        #pragma unroll
        for (int j = 0; j < K; j++) wr[i][j] = w[(c*K + i)*K + j];
    __syncthreads();
    int y = tid >> 3, x0 = (tid & 7) * 4;
    float acc[4] = {0.f, 0.f, 0.f, 0.f};
    #pragma unroll
    for (int i = 0; i < K; i++) {
        float r[SPAN];
        #pragma unroll
        for (int q = 0; q < SPAN; q++) r[q] = s[y + i*DIL][x0 + q];
        #pragma unroll
        for (int j = 0; j < K; j++)
            #pragma unroll
            for (int t = 0; t < 4; t++) acc[t] = fmaf(wr[i][j], r[j*DIL + t], acc[t]);
    }
    *(float4*)&out[((size_t)bc << 10) + y*32 + x0] = make_float4(acc[0],acc[1],acc[2],acc[3]);
}

// ---------------- pointwise conv 128->128, f32x2, 8co x 4y x 2x / thread -----
// 128 threads; block = 32co x 8y x 32x. grid (4, 4, 64).
__global__ void __launch_bounds__(128) pw_conv_kernel(const float* __restrict__ in,
                                                      float* __restrict__ out,
                                                      const float* __restrict__ w,
                                                      int oslot) {
    __shared__ __align__(16) float s_in[16][8][32];
    __shared__ float s_w[32][16];
    int tid = threadIdx.x;
    int co0 = blockIdx.x * 32, y0 = blockIdx.y * 8, b = blockIdx.z;
    int xp = tid & 15, yh = (tid >> 4) & 1, cg = tid >> 5;   // cg 0..3
    ull acc[8][4];
    #pragma unroll
    for (int j = 0; j < 8; j++)
        #pragma unroll
        for (int k = 0; k < 4; k++) acc[j][k] = 0ull;

    for (int cc = 0; cc < CP; cc += 16) {
        { int co = tid >> 2, q = tid & 3;
          float4 v = *(const float4*)&w[(size_t)(co0+co)*CP + cc + q*4];
          s_w[co][q*4+0]=v.x; s_w[co][q*4+1]=v.y; s_w[co][q*4+2]=v.z; s_w[co][q*4+3]=v.w; }
        #pragma unroll
        for (int i = tid; i < 1024; i += 128) {     // float4 units
            int ci = i >> 6, rem = i & 63;
            int y = rem >> 3, h = rem & 7;
            *(float4*)&s_in[ci][y][h*4] =
                *(const float4*)&in[(((size_t)b*CP + cc+ci)*HH + y0+y)*WW + h*4];
        }
        __syncthreads();
        #pragma unroll
        for (int ci = 0; ci < 16; ci++) {
            ull iv[4];
            #pragma unroll
            for (int k = 0; k < 4; k++) iv[k] = *(const ull*)&s_in[ci][yh*4 + k][2*xp];
            #pragma unroll
            for (int j = 0; j < 8; j++) {
                float wv = s_w[cg*8 + j][ci];
                ull wv2 = pack2(wv, wv);
                #pragma unroll
                for (int k = 0; k < 4; k++) ffma2(acc[j][k], wv2, iv[k]);
            }
        }
        __syncthreads();
    }
    #pragma unroll
    for (int j = 0; j < 8; j++) {
        int co = co0 + cg*8 + j;
        float s = 0.f, s2 = 0.f;
        #pragma unroll
        for (int k = 0; k < 4; k++) {
            float v0, v1; unpack2(acc[j][k], v0, v1);
            *(float2*)&out[(((size_t)b*CP + co)*HH + y0 + yh*4 + k)*WW + 2*xp] = make_float2(v0, v1);
            s += v0 + v1; s2 += v0*v0 + v1*v1;
        }
        #pragma unroll
        for (int o = 16; o > 0; o >>= 1) {
            s  += __shfl_xor_sync(0xffffffffu, s,  o);
            s2 += __shfl_xor_sync(0xffffffffu, s2, o);
        }
        if ((tid & 31) == 0 && oslot >= 0) {
            atomicAdd(&g_ssum [oslot*CP + co], (double)s);
            atomicAdd(&g_ssum2[oslot*CP + co], (double)s2);
        }
    }
}

// ---------------- 7x1 conv (KH=7, pad 3), f32x2 x-pair, fused stats ----------
__global__ void __launch_bounds__(256) conv7x1_kernel(const float* __restrict__ in,
                                                      float* __restrict__ out,
                                                      const float* __restrict__ w,
                                                      int oslot) {
    __shared__ __align__(16) float s_in[16][14][32];
    __shared__ float s_w[64][16][7];
    int tid = threadIdx.x;
    int co0 = blockIdx.x * 64, y0 = blockIdx.y * 8, b = blockIdx.z;
    int xp = tid & 15, cg = tid >> 4;
    ull acc[4][8];
    #pragma unroll
    for (int j = 0; j < 4; j++)
        #pragma unroll
        for (int y = 0; y < 8; y++) acc[j][y] = 0ull;

    for (int cc = 0; cc < CP; cc += 16) {
        for (int i = tid; i < 16*14*32; i += 256) {
            int ci = i / 448, rem = i - ci*448;
            int r = rem >> 5, q = rem & 31;
            int y = y0 + r - 3;
            float v = 0.f;
            if (y >= 0 && y < HH) v = in[(((size_t)b*CP + cc+ci)*HH + y)*WW + q];
            s_in[ci][r][q] = v;
        }
        for (int i = tid; i < 64*16*7; i += 256) {
            int co = i / 112, rem = i - co*112;
            int ci = rem / 7, kh = rem - ci*7;
            s_w[co][ci][kh] = w[((size_t)(co0+co)*CP + cc+ci)*7 + kh];
        }
        __syncthreads();
        #pragma unroll 2
        for (int ci = 0; ci < 16; ci++) {
            ull iv[14];
            #pragma unroll
            for (int r = 0; r < 14; r++) iv[r] = *(const ull*)&s_in[ci][r][2*xp];
            #pragma unroll
            for (int j = 0; j < 4; j++) {
                #pragma unroll
                for (int kh = 0; kh < 7; kh++) {
                    float wv = s_w[cg*4 + j][ci][kh];
                    ull wv2 = pack2(wv, wv);
                    #pragma unroll
                    for (int y = 0; y < 8; y++) ffma2(acc[j][y], wv2, iv[y + kh]);
                }
            }
        }
        __syncthreads();
    }
    #pragma unroll
    for (int j = 0; j < 4; j++) {
        int co = co0 + cg*4 + j;
        float s = 0.f, s2 = 0.f;
        #pragma unroll
        for (int y = 0; y < 8; y++) {
            float v0, v1; unpack2(acc[j][y], v0, v1);
            *(float2*)&out[(((size_t)b*CP + co)*HH + y0+y)*WW + 2*xp] = make_float2(v0, v1);
            s += v0 + v1; s2 += v0*v0 + v1*v1;
        }
        #pragma unroll
        for (int o = 1; o < 16; o <<= 1) {
            s  += __shfl_xor_sync(0xffffffffu, s,  o);
            s2 += __shfl_xor_sync(0xffffffffu, s2, o);
        }
        if (xp == 0 && oslot >= 0) {
            atomicAdd(&g_ssum [oslot*CP + co], (double)s);
            atomicAdd(&g_ssum2[oslot*CP + co], (double)s2);
        }
    }
}

// ---------------- 1x7 conv (KW=7, pad 3), relu-in, f32x2 y-pair ---------------
__global__ void __launch_bounds__(256) conv1x7_kernel(const float* __restrict__ in,
                                                      float* __restrict__ out,
                                                      const float* __restrict__ w) {
    __shared__ float s_in[16][8][38];
    __shared__ float s_w[64][16][7];
    int tid = threadIdx.x;
    int co0 = blockIdx.x * 64, y0 = blockIdx.y * 8, b = blockIdx.z;
    int xc = tid & 31, cg = tid >> 5;
    ull acc[8][4];
    #pragma unroll
    for (int j = 0; j < 8; j++)
        #pragma unroll
        for (int yp = 0; yp < 4; yp++) acc[j][yp] = 0ull;

    for (int cc = 0; cc < CP; cc += 16) {
        for (int i = tid; i < 16*8*38; i += 256) {
            int ci = i / 304, rem = i - ci*304;
            int y = rem / 38, q = rem - y*38;
            int xx = q - 3;
            float v = 0.f;
            if (xx >= 0 && xx < WW) {
                v = in[(((size_t)b*CP + cc+ci)*HH + y0+y)*WW + xx];
                v = fmaxf(v, 0.f);
            }
            s_in[ci][y][q] = v;
        }
        for (int i = tid; i < 64*16*7; i += 256) {
            int co = i / 112, rem = i - co*112;
            int ci = rem / 7, kw = rem - ci*7;
            s_w[co][ci][kw] = w[((size_t)(co0+co)*CP + cc+ci)*7 + kw];
        }
        __syncthreads();
        #pragma unroll 2
        for (int ci = 0; ci < 16; ci++) {
            #pragma unroll
            for (int kw = 0; kw < 7; kw++) {
                ull iv[4];
                #pragma unroll
                for (int yp = 0; yp < 4; yp++)
                    iv[yp] = pack2(s_in[ci][2*yp][xc+kw], s_in[ci][2*yp+1][xc+kw]);
                #pragma unroll
                for (int j = 0; j < 8; j++) {
                    float wv = s_w[cg*8 + j][ci][kw];
                    ull wv2 = pack2(wv, wv);
                    #pragma unroll
                    for (int yp = 0; yp < 4; yp++) ffma2(acc[j][yp], wv2, iv[yp]);
                }
            }
        }
        __syncthreads();
    }
    #pragma unroll
    for (int j = 0; j < 8; j++) {
        int co = co0 + cg*8 + j;
        #pragma unroll
        for (int yp = 0; yp < 4; yp++) {
            float v0, v1; unpack2(acc[j][yp], v0, v1);
            out[(((size_t)b*CP + co)*HH + y0+2*yp  )*WW + xc] = v0;
            out[(((size_t)b*CP + co)*HH + y0+2*yp+1)*WW + xc] = v1;
        }
    }
}

// ---------------- final combine + scatter (float4) ----------------------------
__global__ void combine_kernel(const float* __restrict__ wv, float* __restrict__ out) {
    int n4 = blockIdx.x * 256 + threadIdx.x;   // < NSEL/4
    int n = n4 << 2;
    int b = n >> 17, p = (n >> 10) & 127, hw = n & 1023;
    float m0 = g_meanv[0*CP+p],  r0 = g_rstdv[0*CP+p];
    float m1 = g_meanv[1*CP+p],  r1 = g_rstdv[1*CP+p];
    float m3 = g_meanv[3*CP+p],  r3 = g_rstdv[3*CP+p];
    float m5 = g_meanv[5*CP+p],  r5 = g_rstdv[5*CP+p];
    float m7 = g_meanv[7*CP+p],  r7 = g_rstdv[7*CP+p];
    float m8 = g_meanv[8*CP+p],  r8 = g_rstdv[8*CP+p];
    float m9 = g_meanv[9*CP+p],  r9 = g_rstdv[9*CP+p];
    float mA = g_meanv[10*CP+p], rA = g_rstdv[10*CP+p];
    float w1=wv[1],w2=wv[2],w3=wv[3],w4=wv[4],w5=wv[5],w6=wv[6],w7=wv[7],w8=wv[8],w9=wv[9];
    float a[4] = {0.f,0.f,0.f,0.f};
    { float4 v = *(const float4*)&g_bmax[n];  const float* q=(const float*)&v;
      #pragma unroll
      for (int t=0;t<4;t++) a[t] += w1*(q[t]-m0)*r0; }
    { float4 v = *(const float4*)&g_bavg[n];  const float* q=(const float*)&v;
      #pragma unroll
      for (int t=0;t<4;t++) a[t] += w2*(q[t]-m1)*r1; }
    { float4 v = *(const float4*)&g_xtemp[n]; const float* q=(const float*)&v;
      #pragma unroll
      for (int t=0;t<4;t++) a[t] += w3*q[t]; }
    { float4 v = *(const float4*)&g_s3[n];    const float* q=(const float*)&v;
      #pragma unroll
      for (int t=0;t<4;t++) a[t] += w4*(q[t]-m3)*r3; }
    { float4 v = *(const float4*)&g_s5[n];    const float* q=(const float*)&v;
      #pragma unroll
      for (int t=0;t<4;t++) a[t] += w5*(q[t]-m5)*r5; }
    { float4 v = *(const float4*)&g_s7[n];    const float* q=(const float*)&v;
      #pragma unroll
      for (int t=0;t<4;t++) a[t] += w6*(q[t]-m7)*r7; }
    { float4 v = *(const float4*)&g_d3[n];    const float* q=(const float*)&v;
      #pragma unroll
      for (int t=0;t<4;t++) a[t] += w7*(q[t]-m8)*r8; }
    { float4 v = *(const float4*)&g_d5[n];    const float* q=(const float*)&v;
      #pragma unroll
      for (int t=0;t<4;t++) a[t] += w8*(q[t]-m9)*r9; }
    { float4 v = *(const float4*)&g_c7[n];    const float* q=(const float*)&v;
      #pragma unroll
      for (int t=0;t<4;t++) a[t] += w9*(q[t]-mA)*rA; }
    int cs = g_idx[p];
    *(float4*)&out[(((size_t)b*C + cs) << 10) + hw] = make_float4(a[0],a[1],a[2],a[3]);
}

// =============================================================================
extern "C" void kernel_launch(void* const* d_in, const int* in_sizes, int n_in,
                              void* d_out, int out_size) {
    const float* x        = (const float*)d_in[0];
    const float* weights  = (const float*)d_in[1];
    const float* wall     = (const float*)d_in[2];
    const float* w_fc1    = (const float*)d_in[3];
    const float* w_fc2    = (const float*)d_in[4];
    const float* sep3_dw1 = (const float*)d_in[5];
    const float* sep3_pw1 = (const float*)d_in[6];
    const float* sep3_dw2 = (const float*)d_in[7];
    const float* sep3_pw2 = (const float*)d_in[8];
    const float* sep5_dw1 = (const float*)d_in[9];
    const float* sep5_pw1 = (const float*)d_in[10];
    const float* sep5_dw2 = (const float*)d_in[11];
    const float* sep5_pw2 = (const float*)d_in[12];
    const float* sep7_dw1 = (const float*)d_in[13];
    const float* sep7_pw1 = (const float*)d_in[14];
    const float* sep7_dw2 = (const float*)d_in[15];
    const float* sep7_pw2 = (const float*)d_in[16];
    const float* dil3_dw  = (const float*)d_in[17];
    const float* dil3_pw  = (const float*)d_in[18];
    const float* dil5_dw  = (const float*)d_in[19];
    const float* dil5_pw  = (const float*)d_in[20];
    const float* w_1x7    = (const float*)d_in[21];
    const float* w_7x1    = (const float*)d_in[22];
    float* out = (float*)d_out;

    // Resolve REAL device addresses (host shadow symbols are ATS garbage on GB300).
    float *t_xtemp,*t_1,*t_2,*t_bmax,*t_bavg,*t_s3,*t_s5,*t_s7,*t_d3,*t_d5,*t_c7;
    { void* p;
      cudaGetSymbolAddress(&p, g_xtemp); t_xtemp=(float*)p;
      cudaGetSymbolAddress(&p, g_t1);    t_1    =(float*)p;
      cudaGetSymbolAddress(&p, g_t2);    t_2    =(float*)p;
      cudaGetSymbolAddress(&p, g_bmax);  t_bmax =(float*)p;
      cudaGetSymbolAddress(&p, g_bavg);  t_bavg =(float*)p;
      cudaGetSymbolAddress(&p, g_s3);    t_s3   =(float*)p;
      cudaGetSymbolAddress(&p, g_s5);    t_s5   =(float*)p;
      cudaGetSymbolAddress(&p, g_s7);    t_s7   =(float*)p;
      cudaGetSymbolAddress(&p, g_d3);    t_d3   =(float*)p;
      cudaGetSymbolAddress(&p, g_d5);    t_d5   =(float*)p;
      cudaGetSymbolAddress(&p, g_c7);    t_c7   =(float*)p; }

    const int GSEL4 = NSEL / 1024;   // 8192
    const int GALL4 = NALL / 1024;   // 32768
    dim3 gpw(4, 4, B);               // pw: 32co x 8y tiles
    dim3 g7(2, 4, B);                // 7-convs: 64co x 8y tiles
    const int GDW = B * CP;          // 8192

    // 0-2: dependency prefix for conv1x7
    attn_fused_kernel<<<B, 512>>>(x, w_fc1, wall, w_fc2);
    slist_topk_kernel<<<1, C>>>();
    gather4_kernel<<<GSEL4, 256>>>(x);

    // 3: conv1x7 (ncu samples launch index 3)
    conv1x7_kernel<<<g7, 256>>>(t_xtemp, t_1, w_1x7);
    conv7x1_kernel<<<g7, 256>>>(t_1, t_c7, w_7x1, 10);

    // independent passes
    scale4_kernel<<<GALL4, 256>>>(x, out);
    pool3f_kernel<<<GDW, 256>>>(t_xtemp, t_bmax, t_bavg);

    // sep convs: slots mid/fin = (2,3) (4,5) (6,7)
    dw_conv_kernel<3,1,1><<<GDW, 256>>>(t_xtemp, t_1, sep3_dw1, 0);
    pw_conv_kernel<<<gpw, 128>>>(t_1, t_2, sep3_pw1, 2);
    dw_conv_kernel<3,1,2><<<GDW, 256>>>(t_2, t_1, sep3_dw2, 2);
    pw_conv_kernel<<<gpw, 128>>>(t_1, t_s3, sep3_pw2, 3);

    dw_conv_kernel<5,1,1><<<GDW, 256>>>(t_xtemp, t_1, sep5_dw1, 0);
    pw_conv_kernel<<<gpw, 128>>>(t_1, t_2, sep5_pw1, 4);
    dw_conv_kernel<5,1,2><<<GDW, 256>>>(t_2, t_1, sep5_dw2, 4);
    pw_conv_kernel<<<gpw, 128>>>(t_1, t_s5, sep5_pw2, 5);

    dw_conv_kernel<7,1,1><<<GDW, 256>>>(t_xtemp, t_1, sep7_dw1, 0);
    pw_conv_kernel<<<gpw, 128>>>(t_1, t_2, sep7_pw1, 6);
    dw_conv_kernel<7,1,2><<<GDW, 256>>>(t_2, t_1, sep7_dw2, 6);
    pw_conv_kernel<<<gpw, 128>>>(t_1, t_s7, sep7_pw2, 7);

    // dilated convs
    dw_conv_kernel<3,2,1><<<GDW, 256>>>(t_xtemp, t_1, dil3_dw, 0);
    pw_conv_kernel<<<gpw, 128>>>(t_1, t_d3, dil3_pw, 8);
    dw_conv_kernel<5,2,1><<<GDW, 256>>>(t_xtemp, t_1, dil5_dw, 0);
    pw_conv_kernel<<<gpw, 128>>>(t_1, t_d5, dil5_pw, 9);

    // finalize all stats, combine, scatter
    finalize_kernel<<<NSLOT, 128>>>();
    combine_kernel<<<GSEL4, 256>>>(weights, out);
}